// round 15
// baseline (speedup 1.0000x reference)
#include <cuda_runtime.h>
#include <cuda_bf16.h>
#include <math.h>
#include <cstdint>

// RotationalConv2D v15 — GB300 sm_103a — v14 + 6 blocks/SM (85-reg cap)
// Kernel A: per-patch angle float4 (scale-folded) + tf32 B-fragment table.
// Kernel B: smem-free tf32 mma.sync main kernel, flat j-loop unroll 5,
//           __launch_bounds__(128,6) -> 24 warps/SM.

#define HDIM 128
#define CCH 16
#define FOUT 32
#define KK 5
#define HO 124
#define WO 124
#define NP (4 * HO * WO)     // 61504 = 961 * 64
#define HW (HO * WO)

__device__ float4 g_ang[NP];              // (co*s, si*s, xo*s, yo*s)
__device__ uint4  g_bfrag[25 * 4 * 32];   // [j][slot][lane]

__device__ __forceinline__ uint32_t f2tf32(float x) {
    uint32_t r;
    asm("cvt.rn.tf32.f32 %0, %1;" : "=r"(r) : "f"(x));
    return r;
}

__device__ __forceinline__ void mma_tf32(float* c,
                                         uint32_t a0, uint32_t a1,
                                         uint32_t a2, uint32_t a3,
                                         uint32_t b0, uint32_t b1) {
    asm volatile(
        "mma.sync.aligned.m16n8k8.row.col.f32.tf32.tf32.f32 "
        "{%0,%1,%2,%3}, {%4,%5,%6,%7}, {%8,%9}, {%0,%1,%2,%3};"
        : "+f"(c[0]), "+f"(c[1]), "+f"(c[2]), "+f"(c[3])
        : "r"(a0), "r"(a1), "r"(a2), "r"(a3), "r"(b0), "r"(b1));
}

// ---------------- Kernel A: angles (+ W fragments from block 0) ----------------
__global__ void __launch_bounds__(256)
rot_angles_kernel(const float* __restrict__ in, const float* __restrict__ Wg)
{
    const int tid = threadIdx.x;
    const int pp  = tid >> 2;
    const int g   = tid & 3;
    const int P   = blockIdx.x * 64 + pp;

    const int b   = P / HW;
    const int rem = P - b * HW;
    const int ho  = rem / WO;
    const int wo  = rem - ho * WO;
    const float* pb = in + ((b * HDIM + ho) * HDIM + wo) * CCH + g * 4;

    float tot = 0.f, sr = 0.f, sc = 0.f;
    #pragma unroll
    for (int r = 0; r < KK; r++) {
        #pragma unroll
        for (int cl = 0; cl < KK; cl++) {
            float4 v = *reinterpret_cast<const float4*>(pb + (r * HDIM + cl) * CCH);
            float s = v.x + v.y + v.z + v.w;
            tot += s;
            sr  += s * (float)r;
            sc  += s * (float)cl;
        }
    }
    tot += __shfl_xor_sync(0xffffffffu, tot, 1);
    tot += __shfl_xor_sync(0xffffffffu, tot, 2);
    sr  += __shfl_xor_sync(0xffffffffu, sr, 1);
    sr  += __shfl_xor_sync(0xffffffffu, sr, 2);
    sc  += __shfl_xor_sync(0xffffffffu, sc, 1);
    sc  += __shfl_xor_sync(0xffffffffu, sc, 2);

    if (g == 0) {
        tot += 1e-7f;
        const float cr   = sr / tot;
        const float ccen = sc / tot;
        const float m    = (float)(KK - 1) * 0.5f;
        const float ang  = atan2f(cr - m, ccen - m + 1e-7f);
        const float co   = __cosf(ang);
        const float si   = __sinf(ang);
        const float km1  = (float)(KK - 1);
        const float scale = 1.0f / (1.0f + 1e-7f);
        g_ang[P] = make_float4(co * scale, si * scale,
                               (km1 - (co * km1 - si * km1)) * 0.5f * scale,
                               (km1 - (si * km1 + co * km1)) * 0.5f * scale);
    }

    if (blockIdx.x == 0) {
        uint32_t* bf = reinterpret_cast<uint32_t*>(g_bfrag);
        for (int i = tid; i < 25 * 4 * 32 * 4; i += 256) {
            const int r2  = i & 3;
            const int ln  = (i >> 2) & 31;
            const int ntp = (i >> 7) & 1;
            const int ks  = (i >> 8) & 1;
            const int j   = i >> 9;
            const int nt  = 2 * ntp + (r2 >> 1);
            const int r   = r2 & 1;
            bf[i] = f2tf32(Wg[(nt * 8 + (ln >> 2)) * 400 + j * 16 + 4 * (ln & 3) + 2 * ks + r]);
        }
    }
}

// ---------------- Kernel B: main taps + mma ----------------
__global__ void __launch_bounds__(128, 6)
rotconv15_kernel(const float* __restrict__ in,
                 const float* __restrict__ bias,
                 float* __restrict__ out)
{
    const int tid  = threadIdx.x;
    const int wid  = tid >> 5;
    const int lane = tid & 31;
    const int q    = lane & 3;
    const int row  = lane >> 2;
    const int tb   = blockIdx.x * 64 + wid * 16;   // exact grid

    float co[2], si[2], xo[2], yo[2];
    const float* pbase[2];
    #pragma unroll
    for (int u = 0; u < 2; u++) {
        const int P   = tb + row + 8 * u;
        const float4 a = g_ang[P];
        co[u] = a.x; si[u] = a.y; xo[u] = a.z; yo[u] = a.w;
        const int b   = P / HW;
        const int rem = P - b * HW;
        const int ho  = rem / WO;
        const int wo  = rem - ho * WO;
        pbase[u] = in + ((b * HDIM + ho) * HDIM + wo) * CCH + q * 4;
    }

    float acc[4][4];
    #pragma unroll
    for (int nt = 0; nt < 4; nt++)
        #pragma unroll
        for (int k = 0; k < 4; k++) acc[nt][k] = 0.f;

    #pragma unroll 5
    for (int j = 0; j < 25; j++) {
        const int   jy = j / KK;
        const int   jx = j - jy * KK;
        const float gx = (float)jx;
        const float gy = (float)jy;

        const uint4* bp = g_bfrag + j * 4 * 32 + lane;
        const uint4 bk0a = __ldg(bp);
        const uint4 bk0b = __ldg(bp + 32);
        const uint4 bk1a = __ldg(bp + 64);
        const uint4 bk1b = __ldg(bp + 96);

        uint32_t ra[2][4];
        #pragma unroll
        for (int u = 0; u < 2; u++) {
            const float sx  = co[u] * gx - si[u] * gy + xo[u];
            const float sy  = si[u] * gx + co[u] * gy + yo[u];
            const float x0f = floorf(sx);
            const float y0f = floorf(sy);
            const float wx  = sx - x0f;
            const float wy  = sy - y0f;
            const int   x0  = (int)x0f;
            const int   y0  = (int)y0f;
            const int   x1  = x0 + 1;
            const int   y1  = y0 + 1;

            const bool vx0 = (unsigned)x0 < KK;
            const bool vx1 = (unsigned)x1 < KK;
            const bool vy0 = (unsigned)y0 < KK;
            const bool vy1 = (unsigned)y1 < KK;
            const int x0c = min(max(x0, 0), KK - 1);
            const int x1c = min(max(x1, 0), KK - 1);
            const int y0c = min(max(y0, 0), KK - 1);
            const int y1c = min(max(y1, 0), KK - 1);

            const float wx1 = 1.f - wx;
            const float wy1 = 1.f - wy;
            const float w00 = (vx0 && vy0) ? wx1 * wy1 : 0.f;
            const float w01 = (vx1 && vy0) ? wx  * wy1 : 0.f;
            const float w10 = (vx0 && vy1) ? wx1 * wy  : 0.f;
            const float w11 = (vx1 && vy1) ? wx  * wy  : 0.f;

            const float* r0 = pbase[u] + y0c * (HDIM * CCH);
            const float* r1 = pbase[u] + y1c * (HDIM * CCH);
            const float4 v00 = *reinterpret_cast<const float4*>(r0 + x0c * CCH);
            const float4 v01 = *reinterpret_cast<const float4*>(r0 + x1c * CCH);
            const float4 v10 = *reinterpret_cast<const float4*>(r1 + x0c * CCH);
            const float4 v11 = *reinterpret_cast<const float4*>(r1 + x1c * CCH);

            ra[u][0] = f2tf32(w00 * v00.x + w01 * v01.x + w10 * v10.x + w11 * v11.x);
            ra[u][1] = f2tf32(w00 * v00.y + w01 * v01.y + w10 * v10.y + w11 * v11.y);
            ra[u][2] = f2tf32(w00 * v00.z + w01 * v01.z + w10 * v10.z + w11 * v11.z);
            ra[u][3] = f2tf32(w00 * v00.w + w01 * v01.w + w10 * v10.w + w11 * v11.w);
        }

        mma_tf32(acc[0], ra[0][0], ra[1][0], ra[0][1], ra[1][1], bk0a.x, bk0a.y);
        mma_tf32(acc[1], ra[0][0], ra[1][0], ra[0][1], ra[1][1], bk0a.z, bk0a.w);
        mma_tf32(acc[2], ra[0][0], ra[1][0], ra[0][1], ra[1][1], bk0b.x, bk0b.y);
        mma_tf32(acc[3], ra[0][0], ra[1][0], ra[0][1], ra[1][1], bk0b.z, bk0b.w);
        mma_tf32(acc[0], ra[0][2], ra[1][2], ra[0][3], ra[1][3], bk1a.x, bk1a.y);
        mma_tf32(acc[1], ra[0][2], ra[1][2], ra[0][3], ra[1][3], bk1a.z, bk1a.w);
        mma_tf32(acc[2], ra[0][2], ra[1][2], ra[0][3], ra[1][3], bk1b.x, bk1b.y);
        mma_tf32(acc[3], ra[0][2], ra[1][2], ra[0][3], ra[1][3], bk1b.z, bk1b.w);
    }

    #pragma unroll
    for (int nt = 0; nt < 4; nt++) {
        const float2 bv = *reinterpret_cast<const float2*>(bias + nt * 8 + 2 * q);
        float* o0 = out + (tb + row) * FOUT + nt * 8 + 2 * q;
        float* o1 = out + (tb + row + 8) * FOUT + nt * 8 + 2 * q;
        float2 v0, v1;
        v0.x = acc[nt][0] + bv.x;  v0.y = acc[nt][1] + bv.y;
        v1.x = acc[nt][2] + bv.x;  v1.y = acc[nt][3] + bv.y;
        *reinterpret_cast<float2*>(o0) = v0;
        *reinterpret_cast<float2*>(o1) = v1;
    }
}

extern "C" void kernel_launch(void* const* d_in, const int* in_sizes, int n_in,
                              void* d_out, int out_size)
{
    const float* in   = (const float*)d_in[0];   // [4,128,128,16]
    const float* Wg   = (const float*)d_in[1];   // [32,5,5,16]
    const float* bias = (const float*)d_in[2];   // [32]
    float* out = (float*)d_out;                  // [4,124,124,32]

    rot_angles_kernel<<<NP / 64, 256>>>(in, Wg);          // 961 blocks
    rotconv15_kernel<<<NP / 64, 128>>>(in, bias, out);    // 961 blocks
}

// round 16
// speedup vs baseline: 1.0801x; 1.0801x over previous
#include <cuda_runtime.h>
#include <cuda_bf16.h>
#include <math.h>
#include <cstdint>

// RotationalConv2D v16 — GB300 sm_103a — smem-staged taps + tf32 mma.sync
// Kernel A: per-patch angles (scale-folded) + tf32 B-fragment table (as v14).
// Kernel B: 2D tiles: block = 4 ho x 16 wo patches; warp = one ho row, M=16
//           along wo. Input union region (8 rows x 20 cols x 16ch = 10KB)
//           staged coalesced into smem with 80B pixel stride -> every tap
//           LDS.128 is exactly 4 wavefronts. jy rolled, jx unrolled (v14 ILP).

#define HDIM 128
#define CCH 16
#define FOUT 32
#define KK 5
#define HO 124
#define WO 124
#define NP (4 * HO * WO)     // 61504
#define HW (HO * WO)
#define SROWS 8
#define SCOLS 20
#define PIXB 80              // bytes per pixel slot (64 data + 16 pad)

__device__ float4 g_ang[NP];              // (co*s, si*s, xo*s, yo*s)
__device__ uint4  g_bfrag[25 * 4 * 32];   // [j][slot][lane]

__device__ __forceinline__ uint32_t f2tf32(float x) {
    uint32_t r;
    asm("cvt.rn.tf32.f32 %0, %1;" : "=r"(r) : "f"(x));
    return r;
}

__device__ __forceinline__ void mma_tf32(float* c,
                                         uint32_t a0, uint32_t a1,
                                         uint32_t a2, uint32_t a3,
                                         uint32_t b0, uint32_t b1) {
    asm volatile(
        "mma.sync.aligned.m16n8k8.row.col.f32.tf32.tf32.f32 "
        "{%0,%1,%2,%3}, {%4,%5,%6,%7}, {%8,%9}, {%0,%1,%2,%3};"
        : "+f"(c[0]), "+f"(c[1]), "+f"(c[2]), "+f"(c[3])
        : "r"(a0), "r"(a1), "r"(a2), "r"(a3), "r"(b0), "r"(b1));
}

// ---------------- Kernel A: angles (+ W fragments from block 0) ----------------
__global__ void __launch_bounds__(256)
rot_angles_kernel(const float* __restrict__ in, const float* __restrict__ Wg)
{
    const int tid = threadIdx.x;
    const int pp  = tid >> 2;
    const int g   = tid & 3;
    const int P   = blockIdx.x * 64 + pp;

    const int b   = P / HW;
    const int rem = P - b * HW;
    const int ho  = rem / WO;
    const int wo  = rem - ho * WO;
    const float* pb = in + ((b * HDIM + ho) * HDIM + wo) * CCH + g * 4;

    float tot = 0.f, sr = 0.f, sc = 0.f;
    #pragma unroll
    for (int r = 0; r < KK; r++) {
        #pragma unroll
        for (int cl = 0; cl < KK; cl++) {
            float4 v = *reinterpret_cast<const float4*>(pb + (r * HDIM + cl) * CCH);
            float s = v.x + v.y + v.z + v.w;
            tot += s;
            sr  += s * (float)r;
            sc  += s * (float)cl;
        }
    }
    tot += __shfl_xor_sync(0xffffffffu, tot, 1);
    tot += __shfl_xor_sync(0xffffffffu, tot, 2);
    sr  += __shfl_xor_sync(0xffffffffu, sr, 1);
    sr  += __shfl_xor_sync(0xffffffffu, sr, 2);
    sc  += __shfl_xor_sync(0xffffffffu, sc, 1);
    sc  += __shfl_xor_sync(0xffffffffu, sc, 2);

    if (g == 0) {
        tot += 1e-7f;
        const float cr   = sr / tot;
        const float ccen = sc / tot;
        const float m    = (float)(KK - 1) * 0.5f;
        const float ang  = atan2f(cr - m, ccen - m + 1e-7f);
        const float co   = __cosf(ang);
        const float si   = __sinf(ang);
        const float km1  = (float)(KK - 1);
        const float scale = 1.0f / (1.0f + 1e-7f);
        g_ang[P] = make_float4(co * scale, si * scale,
                               (km1 - (co * km1 - si * km1)) * 0.5f * scale,
                               (km1 - (si * km1 + co * km1)) * 0.5f * scale);
    }

    if (blockIdx.x == 0) {
        uint32_t* bf = reinterpret_cast<uint32_t*>(g_bfrag);
        for (int i = tid; i < 25 * 4 * 32 * 4; i += 256) {
            const int r2  = i & 3;
            const int ln  = (i >> 2) & 31;
            const int ntp = (i >> 7) & 1;
            const int ks  = (i >> 8) & 1;
            const int j   = i >> 9;
            const int nt  = 2 * ntp + (r2 >> 1);
            const int r   = r2 & 1;
            bf[i] = f2tf32(Wg[(nt * 8 + (ln >> 2)) * 400 + j * 16 + 4 * (ln & 3) + 2 * ks + r]);
        }
    }
}

// ---------------- Kernel B: smem-staged taps + mma ----------------
__global__ void __launch_bounds__(128, 5)
rotconv16_kernel(const float* __restrict__ in,
                 const float* __restrict__ bias,
                 float* __restrict__ out)
{
    __shared__ char smc[SROWS * SCOLS * PIXB];   // 12800 B

    const int tid  = threadIdx.x;
    const int wid  = tid >> 5;
    const int lane = tid & 31;
    const int q    = lane & 3;
    const int row  = lane >> 2;

    // grid: bi = ((b*31 + ht) << 3) | wt
    const int bi  = blockIdx.x;
    const int wt  = bi & 7;
    const int rst = bi >> 3;
    const int ht  = rst % 31;
    const int b   = rst / 31;
    const int ho0 = ht * 4;
    const int wo0 = wt * 16;

    // --- stage input region: rows ho0..ho0+7, cols wo0..wo0+19 (col-clamped) ---
    #pragma unroll
    for (int it = 0; it < 5; it++) {
        const int i   = tid + it * 128;          // 0..639 float4s
        const int pix = i >> 2;
        const int c4  = i & 3;
        const int r   = pix / SCOLS;
        const int c   = pix - r * SCOLS;
        const int gc  = min(wo0 + c, HDIM - 1);
        const float4 v = *reinterpret_cast<const float4*>(
            in + (((b * HDIM) + ho0 + r) * HDIM + gc) * CCH + c4 * 4);
        *reinterpret_cast<float4*>(smc + pix * PIXB + c4 * 16) = v;
    }
    __syncthreads();

    // --- per-patch setup: warp handles ho = ho0+wid, wo = wo0 + row + 8u ---
    const int ho = ho0 + wid;
    float co[2], si[2], xo[2], yo[2];
    uint32_t sbase[2];
    int wo_u[2];
    #pragma unroll
    for (int u = 0; u < 2; u++) {
        const int wo_raw = wo0 + row + 8 * u;
        const int woc    = min(wo_raw, WO - 1);
        wo_u[u] = wo_raw;
        const float4 a = g_ang[(b * HO + ho) * WO + woc];
        co[u] = a.x; si[u] = a.y; xo[u] = a.z; yo[u] = a.w;
        // smem base for this patch: row wid, col (woc - wo0), channel quad q
        sbase[u] = (uint32_t)((wid * SCOLS + (woc - wo0)) * PIXB + q * 16);
    }

    float acc[4][4];
    #pragma unroll
    for (int nt = 0; nt < 4; nt++)
        #pragma unroll
        for (int k = 0; k < 4; k++) acc[nt][k] = 0.f;

    #pragma unroll 1
    for (int jy = 0; jy < KK; jy++) {
        const float gy = (float)jy;
        float Ax[2], By[2];
        #pragma unroll
        for (int u = 0; u < 2; u++) {
            Ax[u] = xo[u] - si[u] * gy;
            By[u] = yo[u] + co[u] * gy;
        }
        #pragma unroll
        for (int jx = 0; jx < KK; jx++) {
            const int   j  = jy * KK + jx;
            const float gx = (float)jx;

            const uint4* bp = g_bfrag + j * 4 * 32 + lane;
            const uint4 bk0a = __ldg(bp);
            const uint4 bk0b = __ldg(bp + 32);
            const uint4 bk1a = __ldg(bp + 64);
            const uint4 bk1b = __ldg(bp + 96);

            uint32_t ra[2][4];
            #pragma unroll
            for (int u = 0; u < 2; u++) {
                const float sx  = co[u] * gx + Ax[u];
                const float sy  = si[u] * gx + By[u];
                const float x0f = floorf(sx);
                const float y0f = floorf(sy);
                const float wx  = sx - x0f;
                const float wy  = sy - y0f;
                const int   x0  = (int)x0f;
                const int   y0  = (int)y0f;
                const int   x1  = x0 + 1;
                const int   y1  = y0 + 1;

                const bool vx0 = (unsigned)x0 < KK;
                const bool vx1 = (unsigned)x1 < KK;
                const bool vy0 = (unsigned)y0 < KK;
                const bool vy1 = (unsigned)y1 < KK;
                const int x0c = min(max(x0, 0), KK - 1);
                const int x1c = min(max(x1, 0), KK - 1);
                const int y0c = min(max(y0, 0), KK - 1);
                const int y1c = min(max(y1, 0), KK - 1);

                const float wx1 = 1.f - wx;
                const float wy1 = 1.f - wy;
                const float w00 = (vx0 && vy0) ? wx1 * wy1 : 0.f;
                const float w01 = (vx1 && vy0) ? wx  * wy1 : 0.f;
                const float w10 = (vx0 && vy1) ? wx1 * wy  : 0.f;
                const float w11 = (vx1 && vy1) ? wx  * wy  : 0.f;

                // smem taps: row offset = y*SCOLS pixels, col offset = x pixels
                const uint32_t r0o = sbase[u] + (uint32_t)(y0c * (SCOLS * PIXB));
                const uint32_t r1o = sbase[u] + (uint32_t)(y1c * (SCOLS * PIXB));
                const float4 v00 = *reinterpret_cast<const float4*>(smc + r0o + x0c * PIXB);
                const float4 v01 = *reinterpret_cast<const float4*>(smc + r0o + x1c * PIXB);
                const float4 v10 = *reinterpret_cast<const float4*>(smc + r1o + x0c * PIXB);
                const float4 v11 = *reinterpret_cast<const float4*>(smc + r1o + x1c * PIXB);

                ra[u][0] = f2tf32(w00 * v00.x + w01 * v01.x + w10 * v10.x + w11 * v11.x);
                ra[u][1] = f2tf32(w00 * v00.y + w01 * v01.y + w10 * v10.y + w11 * v11.y);
                ra[u][2] = f2tf32(w00 * v00.z + w01 * v01.z + w10 * v10.z + w11 * v11.z);
                ra[u][3] = f2tf32(w00 * v00.w + w01 * v01.w + w10 * v10.w + w11 * v11.w);
            }

            mma_tf32(acc[0], ra[0][0], ra[1][0], ra[0][1], ra[1][1], bk0a.x, bk0a.y);
            mma_tf32(acc[1], ra[0][0], ra[1][0], ra[0][1], ra[1][1], bk0a.z, bk0a.w);
            mma_tf32(acc[2], ra[0][0], ra[1][0], ra[0][1], ra[1][1], bk0b.x, bk0b.y);
            mma_tf32(acc[3], ra[0][0], ra[1][0], ra[0][1], ra[1][1], bk0b.z, bk0b.w);
            mma_tf32(acc[0], ra[0][2], ra[1][2], ra[0][3], ra[1][3], bk1a.x, bk1a.y);
            mma_tf32(acc[1], ra[0][2], ra[1][2], ra[0][3], ra[1][3], bk1a.z, bk1a.w);
            mma_tf32(acc[2], ra[0][2], ra[1][2], ra[0][3], ra[1][3], bk1b.x, bk1b.y);
            mma_tf32(acc[3], ra[0][2], ra[1][2], ra[0][3], ra[1][3], bk1b.z, bk1b.w);
        }
    }

    // --- epilogue: store with wo guard (last wo-tile clamps) ---
    #pragma unroll
    for (int u = 0; u < 2; u++) {
        if (wo_u[u] < WO) {
            const int P = (b * HO + ho) * WO + wo_u[u];
            float* op = out + P * FOUT + 2 * q;
            #pragma unroll
            for (int nt = 0; nt < 4; nt++) {
                const float2 bv = *reinterpret_cast<const float2*>(bias + nt * 8 + 2 * q);
                float2 v;
                v.x = acc[nt][2 * u + 0] + bv.x;
                v.y = acc[nt][2 * u + 1] + bv.y;
                *reinterpret_cast<float2*>(op + nt * 8) = v;
            }
        }
    }
}

extern "C" void kernel_launch(void* const* d_in, const int* in_sizes, int n_in,
                              void* d_out, int out_size)
{
    const float* in   = (const float*)d_in[0];   // [4,128,128,16]
    const float* Wg   = (const float*)d_in[1];   // [32,5,5,16]
    const float* bias = (const float*)d_in[2];   // [32]
    float* out = (float*)d_out;                  // [4,124,124,32]

    rot_angles_kernel<<<NP / 64, 256>>>(in, Wg);            // 961 blocks
    rotconv16_kernel<<<4 * 31 * 8, 128>>>(in, bias, out);   // 992 blocks
}

// round 17
// speedup vs baseline: 1.1504x; 1.0651x over previous
#include <cuda_runtime.h>
#include <cuda_bf16.h>
#include <math.h>
#include <cstdint>

// RotationalConv2D v17 — GB300 sm_103a — v14 + j-split warp pairs (no staging)
// Kernel A: per-patch angle float4 (scale-folded) + tf32 B-fragment table.
// Kernel B: block = 128 thr / 32 patches (2 tiles of 16). Warp w: tile=w>>1,
//           j-half=w&1 (j 0-12 vs 13-24, fully unrolled compile-time bodies).
//           C fragments of the two halves combined via 4KB smem reduce.

#define HDIM 128
#define CCH 16
#define FOUT 32
#define KK 5
#define HO 124
#define WO 124
#define NP (4 * HO * WO)     // 61504 = 1922 * 32
#define HW (HO * WO)

__device__ float4 g_ang[NP];              // (co*s, si*s, xo*s, yo*s)
__device__ uint4  g_bfrag[25 * 4 * 32];   // [j][slot][lane]

__device__ __forceinline__ uint32_t f2tf32(float x) {
    uint32_t r;
    asm("cvt.rn.tf32.f32 %0, %1;" : "=r"(r) : "f"(x));
    return r;
}

__device__ __forceinline__ void mma_tf32(float* c,
                                         uint32_t a0, uint32_t a1,
                                         uint32_t a2, uint32_t a3,
                                         uint32_t b0, uint32_t b1) {
    asm volatile(
        "mma.sync.aligned.m16n8k8.row.col.f32.tf32.tf32.f32 "
        "{%0,%1,%2,%3}, {%4,%5,%6,%7}, {%8,%9}, {%0,%1,%2,%3};"
        : "+f"(c[0]), "+f"(c[1]), "+f"(c[2]), "+f"(c[3])
        : "r"(a0), "r"(a1), "r"(a2), "r"(a3), "r"(b0), "r"(b1));
}

// ---------------- Kernel A: angles (+ W fragments from block 0) ----------------
__global__ void __launch_bounds__(256)
rot_angles_kernel(const float* __restrict__ in, const float* __restrict__ Wg)
{
    const int tid = threadIdx.x;
    const int pp  = tid >> 2;
    const int g   = tid & 3;
    const int P   = blockIdx.x * 64 + pp;

    const int b   = P / HW;
    const int rem = P - b * HW;
    const int ho  = rem / WO;
    const int wo  = rem - ho * WO;
    const float* pb = in + ((b * HDIM + ho) * HDIM + wo) * CCH + g * 4;

    float tot = 0.f, sr = 0.f, sc = 0.f;
    #pragma unroll
    for (int r = 0; r < KK; r++) {
        #pragma unroll
        for (int cl = 0; cl < KK; cl++) {
            float4 v = *reinterpret_cast<const float4*>(pb + (r * HDIM + cl) * CCH);
            float s = v.x + v.y + v.z + v.w;
            tot += s;
            sr  += s * (float)r;
            sc  += s * (float)cl;
        }
    }
    tot += __shfl_xor_sync(0xffffffffu, tot, 1);
    tot += __shfl_xor_sync(0xffffffffu, tot, 2);
    sr  += __shfl_xor_sync(0xffffffffu, sr, 1);
    sr  += __shfl_xor_sync(0xffffffffu, sr, 2);
    sc  += __shfl_xor_sync(0xffffffffu, sc, 1);
    sc  += __shfl_xor_sync(0xffffffffu, sc, 2);

    if (g == 0) {
        tot += 1e-7f;
        const float cr   = sr / tot;
        const float ccen = sc / tot;
        const float m    = (float)(KK - 1) * 0.5f;
        const float ang  = atan2f(cr - m, ccen - m + 1e-7f);
        const float co   = __cosf(ang);
        const float si   = __sinf(ang);
        const float km1  = (float)(KK - 1);
        const float scale = 1.0f / (1.0f + 1e-7f);
        g_ang[P] = make_float4(co * scale, si * scale,
                               (km1 - (co * km1 - si * km1)) * 0.5f * scale,
                               (km1 - (si * km1 + co * km1)) * 0.5f * scale);
    }

    if (blockIdx.x == 0) {
        uint32_t* bf = reinterpret_cast<uint32_t*>(g_bfrag);
        for (int i = tid; i < 25 * 4 * 32 * 4; i += 256) {
            const int r2  = i & 3;
            const int ln  = (i >> 2) & 31;
            const int ntp = (i >> 7) & 1;
            const int ks  = (i >> 8) & 1;
            const int j   = i >> 9;
            const int nt  = 2 * ntp + (r2 >> 1);
            const int r   = r2 & 1;
            bf[i] = f2tf32(Wg[(nt * 8 + (ln >> 2)) * 400 + j * 16 + 4 * (ln & 3) + 2 * ks + r]);
        }
    }
}

// ---------------- Kernel B: j-split main taps + mma ----------------
__global__ void __launch_bounds__(128, 5)
rotconv17_kernel(const float* __restrict__ in,
                 const float* __restrict__ bias,
                 float* __restrict__ out)
{
    __shared__ float red[2][16][32];     // [tile][ntk][lane], 4096 B

    const int tid  = threadIdx.x;
    const int wid  = tid >> 5;
    const int lane = tid & 31;
    const int q    = lane & 3;
    const int row  = lane >> 2;
    const int tile = wid >> 1;
    const int half = wid & 1;
    const int tb   = blockIdx.x * 32 + tile * 16;   // exact grid

    float co[2], si[2], xo[2], yo[2];
    const float* pbase[2];
    #pragma unroll
    for (int u = 0; u < 2; u++) {
        const int P   = tb + row + 8 * u;
        const float4 a = g_ang[P];
        co[u] = a.x; si[u] = a.y; xo[u] = a.z; yo[u] = a.w;
        const int b   = P / HW;
        const int rem = P - b * HW;
        const int ho  = rem / WO;
        const int wo  = rem - ho * WO;
        pbase[u] = in + ((b * HDIM + ho) * HDIM + wo) * CCH + q * 4;
    }

    float acc[4][4];
    #pragma unroll
    for (int nt = 0; nt < 4; nt++)
        #pragma unroll
        for (int k = 0; k < 4; k++) acc[nt][k] = 0.f;

    auto jbody = [&](const int j) {
        const float gx = (float)(j % KK);
        const float gy = (float)(j / KK);

        const uint4* bp = g_bfrag + j * 4 * 32 + lane;
        const uint4 bk0a = __ldg(bp);
        const uint4 bk0b = __ldg(bp + 32);
        const uint4 bk1a = __ldg(bp + 64);
        const uint4 bk1b = __ldg(bp + 96);

        uint32_t ra[2][4];
        #pragma unroll
        for (int u = 0; u < 2; u++) {
            const float sx  = co[u] * gx - si[u] * gy + xo[u];
            const float sy  = si[u] * gx + co[u] * gy + yo[u];
            const float x0f = floorf(sx);
            const float y0f = floorf(sy);
            const float wx  = sx - x0f;
            const float wy  = sy - y0f;
            const int   x0  = (int)x0f;
            const int   y0  = (int)y0f;
            const int   x1  = x0 + 1;
            const int   y1  = y0 + 1;

            const bool vx0 = (unsigned)x0 < KK;
            const bool vx1 = (unsigned)x1 < KK;
            const bool vy0 = (unsigned)y0 < KK;
            const bool vy1 = (unsigned)y1 < KK;
            const int x0c = min(max(x0, 0), KK - 1);
            const int x1c = min(max(x1, 0), KK - 1);
            const int y0c = min(max(y0, 0), KK - 1);
            const int y1c = min(max(y1, 0), KK - 1);

            const float wx1 = 1.f - wx;
            const float wy1 = 1.f - wy;
            const float w00 = (vx0 && vy0) ? wx1 * wy1 : 0.f;
            const float w01 = (vx1 && vy0) ? wx  * wy1 : 0.f;
            const float w10 = (vx0 && vy1) ? wx1 * wy  : 0.f;
            const float w11 = (vx1 && vy1) ? wx  * wy  : 0.f;

            const float* r0 = pbase[u] + y0c * (HDIM * CCH);
            const float* r1 = pbase[u] + y1c * (HDIM * CCH);
            const float4 v00 = *reinterpret_cast<const float4*>(r0 + x0c * CCH);
            const float4 v01 = *reinterpret_cast<const float4*>(r0 + x1c * CCH);
            const float4 v10 = *reinterpret_cast<const float4*>(r1 + x0c * CCH);
            const float4 v11 = *reinterpret_cast<const float4*>(r1 + x1c * CCH);

            ra[u][0] = f2tf32(w00 * v00.x + w01 * v01.x + w10 * v10.x + w11 * v11.x);
            ra[u][1] = f2tf32(w00 * v00.y + w01 * v01.y + w10 * v10.y + w11 * v11.y);
            ra[u][2] = f2tf32(w00 * v00.z + w01 * v01.z + w10 * v10.z + w11 * v11.z);
            ra[u][3] = f2tf32(w00 * v00.w + w01 * v01.w + w10 * v10.w + w11 * v11.w);
        }

        mma_tf32(acc[0], ra[0][0], ra[1][0], ra[0][1], ra[1][1], bk0a.x, bk0a.y);
        mma_tf32(acc[1], ra[0][0], ra[1][0], ra[0][1], ra[1][1], bk0a.z, bk0a.w);
        mma_tf32(acc[2], ra[0][0], ra[1][0], ra[0][1], ra[1][1], bk0b.x, bk0b.y);
        mma_tf32(acc[3], ra[0][0], ra[1][0], ra[0][1], ra[1][1], bk0b.z, bk0b.w);
        mma_tf32(acc[0], ra[0][2], ra[1][2], ra[0][3], ra[1][3], bk1a.x, bk1a.y);
        mma_tf32(acc[1], ra[0][2], ra[1][2], ra[0][3], ra[1][3], bk1a.z, bk1a.w);
        mma_tf32(acc[2], ra[0][2], ra[1][2], ra[0][3], ra[1][3], bk1b.x, bk1b.y);
        mma_tf32(acc[3], ra[0][2], ra[1][2], ra[0][3], ra[1][3], bk1b.z, bk1b.w);
    };

    if (half == 0) {
        #pragma unroll
        for (int j = 0; j < 13; j++) jbody(j);
    } else {
        #pragma unroll
        for (int j = 13; j < 25; j++) jbody(j);
    }

    // --- combine halves via smem (odd half publishes, even half finalizes) ---
    if (half) {
        #pragma unroll
        for (int nt = 0; nt < 4; nt++)
            #pragma unroll
            for (int k = 0; k < 4; k++)
                red[tile][nt * 4 + k][lane] = acc[nt][k];
    }
    __syncthreads();
    if (!half) {
        #pragma unroll
        for (int nt = 0; nt < 4; nt++)
            #pragma unroll
            for (int k = 0; k < 4; k++)
                acc[nt][k] += red[tile][nt * 4 + k][lane];

        #pragma unroll
        for (int nt = 0; nt < 4; nt++) {
            const float2 bv = *reinterpret_cast<const float2*>(bias + nt * 8 + 2 * q);
            float* o0 = out + (tb + row) * FOUT + nt * 8 + 2 * q;
            float* o1 = out + (tb + row + 8) * FOUT + nt * 8 + 2 * q;
            float2 v0, v1;
            v0.x = acc[nt][0] + bv.x;  v0.y = acc[nt][1] + bv.y;
            v1.x = acc[nt][2] + bv.x;  v1.y = acc[nt][3] + bv.y;
            *reinterpret_cast<float2*>(o0) = v0;
            *reinterpret_cast<float2*>(o1) = v1;
        }
    }
}

extern "C" void kernel_launch(void* const* d_in, const int* in_sizes, int n_in,
                              void* d_out, int out_size)
{
    const float* in   = (const float*)d_in[0];   // [4,128,128,16]
    const float* Wg   = (const float*)d_in[1];   // [32,5,5,16]
    const float* bias = (const float*)d_in[2];   // [32]
    float* out = (float*)d_out;                  // [4,124,124,32]

    rot_angles_kernel<<<NP / 64, 256>>>(in, Wg);          // 961 blocks
    rotconv17_kernel<<<NP / 32, 128>>>(in, bias, out);    // 1922 blocks
}